// round 15
// baseline (speedup 1.0000x reference)
#include <cuda_runtime.h>
#include <cuda_bf16.h>
#include <math.h>
#include <stdint.h>

#define NB   4
#define SEQ  2048
#define DIM  1024
#define NH   16
#define DKH  64
#define MTOT (NB*SEQ)        // 8192
#define KTILES (DIM/16)      // 64

// Scratch (device globals: no allocations allowed)
__device__ float2 g_cs[SEQ*(DKH/2)];                           // (cos,sin)
__device__ __nv_bfloat16 g_xh[MTOT*DIM],  g_xl[MTOT*DIM];      // input x split
__device__ __nv_bfloat16 g_wh[4*DIM*DIM], g_wl[4*DIM*DIM];     // Wq,Wk,Wv,Wo split
__device__ __nv_bfloat16 g_qh[NB*NH*SEQ*DKH], g_ql[NB*NH*SEQ*DKH];
__device__ __nv_bfloat16 g_kh[NB*NH*SEQ*DKH], g_kl[NB*NH*SEQ*DKH];
__device__ __nv_bfloat16 g_vh[NB*NH*SEQ*DKH], g_vl[NB*NH*SEQ*DKH];
__device__ __nv_bfloat16 g_ath[NB*NH*SEQ*DKH], g_atl[NB*NH*SEQ*DKH];  // attn out

// ---------------------------------------------------------------------------
// Helpers
// ---------------------------------------------------------------------------
__device__ __forceinline__ uint32_t bf2(float lo, float hi) {
    uint32_t r;
    asm("cvt.rn.bf16x2.f32 %0, %1, %2;" : "=r"(r) : "f"(hi), "f"(lo));
    return r;
}

__device__ __forceinline__ uint32_t smem_u32(const void* p) {
    uint32_t a;
    asm("{ .reg .u64 t; cvta.to.shared.u64 t, %1; cvt.u32.u64 %0, t; }"
        : "=r"(a) : "l"(p));
    return a;
}

__device__ __forceinline__ void cpasync16(uint32_t dst, const void* src) {
    asm volatile("cp.async.cg.shared.global [%0], [%1], 16;"
                 :: "r"(dst), "l"(src));
}

__device__ __forceinline__ void ldsm4(uint32_t& r0, uint32_t& r1,
                                      uint32_t& r2, uint32_t& r3, uint32_t a) {
    asm volatile("ldmatrix.sync.aligned.m8n8.x4.shared.b16 {%0,%1,%2,%3}, [%4];"
                 : "=r"(r0), "=r"(r1), "=r"(r2), "=r"(r3) : "r"(a));
}
__device__ __forceinline__ void ldsm4t(uint32_t& r0, uint32_t& r1,
                                       uint32_t& r2, uint32_t& r3, uint32_t a) {
    asm volatile("ldmatrix.sync.aligned.m8n8.x4.trans.shared.b16 {%0,%1,%2,%3}, [%4];"
                 : "=r"(r0), "=r"(r1), "=r"(r2), "=r"(r3) : "r"(a));
}

// NOTE: not volatile — pure register op; "+f" outputs carry all true deps,
// letting nvcc/ptxas interleave independent HMMAs to hide latency.
__device__ __forceinline__ void mma16816(float d[4],
                                         uint32_t a0, uint32_t a1, uint32_t a2, uint32_t a3,
                                         uint32_t b0, uint32_t b1) {
    asm("mma.sync.aligned.m16n8k16.row.col.f32.bf16.bf16.f32 "
        "{%0,%1,%2,%3}, {%4,%5,%6,%7}, {%8,%9}, {%0,%1,%2,%3};"
        : "+f"(d[0]), "+f"(d[1]), "+f"(d[2]), "+f"(d[3])
        : "r"(a0), "r"(a1), "r"(a2), "r"(a3), "r"(b0), "r"(b1));
}

// swizzled address of a 16B unit in a [rows][8 units(128B)] region,
// laid out for ldmatrix x4 of a 16-row x 2-unit tile at (row0, cbase).
__device__ __forceinline__ uint32_t lda(uint32_t base, int row0, int cbase, int lane) {
    int g = lane >> 3, r = lane & 7;
    int row = row0 + ((g & 1) << 3) + r;
    int c = cbase + (g >> 1);
    return base + (((row << 3) + (c ^ (row & 7))) << 4);
}

// ---------------------------------------------------------------------------
// RoPE table (packed cos/sin)
// ---------------------------------------------------------------------------
__global__ void rope_table_kernel(const int* __restrict__ pos) {
    int idx = blockIdx.x * blockDim.x + threadIdx.x;
    if (idx >= SEQ * (DKH/2)) return;
    int srow = idx >> 5;
    int i    = idx & 31;
    double freq = exp(-((double)(2*i) / (double)DKH) * log(10000.0));
    double ang  = (double)pos[srow] * freq;
    g_cs[idx] = make_float2((float)cos(ang), (float)sin(ang));
}

// ---------------------------------------------------------------------------
// Pre-split kernels: fp32 -> bf16 hi/lo planes
// ---------------------------------------------------------------------------
__global__ void split_x_kernel(const float* __restrict__ x) {
    int idx = blockIdx.x * blockDim.x + threadIdx.x;   // < MTOT*DIM/2
    float2 v = *(const float2*)(x + idx * 2);
    uint32_t h = bf2(v.x, v.y);
    float fe = __uint_as_float(h << 16);
    float fo = __uint_as_float(h & 0xffff0000u);
    ((uint32_t*)g_xh)[idx] = h;
    ((uint32_t*)g_xl)[idx] = bf2(v.x - fe, v.y - fo);
}

__global__ void split_w_kernel(const float* __restrict__ Wq,
                               const float* __restrict__ Wk,
                               const float* __restrict__ Wv,
                               const float* __restrict__ Wo) {
    int idx = blockIdx.x * blockDim.x + threadIdx.x;   // < 4*DIM*DIM/2
    int t = idx >> 19;
    int r = idx & ((1 << 19) - 1);
    const float* W = (t == 0) ? Wq : (t == 1) ? Wk : (t == 2) ? Wv : Wo;
    float2 v = *(const float2*)(W + r * 2);
    uint32_t h = bf2(v.x, v.y);
    float fe = __uint_as_float(h << 16);
    float fo = __uint_as_float(h & 0xffff0000u);
    ((uint32_t*)g_wh)[idx] = h;
    ((uint32_t*)g_wl)[idx] = bf2(v.x - fe, v.y - fo);
}

// ---------------------------------------------------------------------------
// cp.async 3-stage pipelined raw-mma NT GEMM on pre-split planes, 3-pass,
// single sync per iteration, pass-major HMMA issue order.
// Block 128x128, BK=16, 8 warps (warp tile 32x64). 48KB static smem.
// Stage row r (128B): units [0-1]=Ah, [2-3]=Bh, [4-5]=Al, [6-7]=Bl (swizzled).
// AMODE 0 (QKV): A = g_xh/g_xl; epilogue applies RoPE (widx<2) and writes
//                split bf16 planes g_{q,k,v}{h,l} in bhsd layout.
// AMODE 1 (Wo):  A = g_ath/g_atl bhsd gather; epilogue writes fp32 out.
// ---------------------------------------------------------------------------
#define STG 16384

template<int AMODE>
__device__ __forceinline__ void load_stage(uint32_t sb, int stage, int kt,
                                           int bm, int bn, int widx, int tid) {
    uint32_t st = sb + stage * STG;
    #pragma unroll
    for (int j = 0; j < 4; ++j) {
        int c   = tid + j * 256;           // 0..1023
        int row = c >> 3;
        int u   = c & 7;
        int k   = kt * 16 + (u & 1) * 8;
        const __nv_bfloat16* src;
        if ((u & 6) == 2) {
            src = g_wh + widx * (DIM * DIM) + (bn * 128 + row) * DIM + k;
        } else if ((u & 6) == 6) {
            src = g_wl + widx * (DIM * DIM) + (bn * 128 + row) * DIM + k;
        } else {
            const __nv_bfloat16* base;
            if (AMODE == 0) base = (u & 4) ? g_xl : g_xh;
            else            base = (u & 4) ? g_atl : g_ath;
            int aRow = bm * 128 + row;
            if (AMODE == 0) {
                src = base + aRow * DIM + k;
            } else {
                int head = k >> 6, koff = k & 63;
                int bq = aRow >> 11, srow = aRow & (SEQ - 1);
                src = base + (((bq << 4) + head) * SEQ + srow) * DKH + koff;
            }
        }
        uint32_t dst = st + (((row << 3) + (u ^ (row & 7))) << 4);
        cpasync16(dst, src);
    }
}

template<int AMODE>
__global__ __launch_bounds__(256, 2)
void gemm_pipe_kernel(float* __restrict__ Cout) {
    __shared__ __align__(16) char smem[3 * STG];   // 48KB

    int widx, bn;
    if (AMODE == 0) { widx = blockIdx.x >> 3; bn = blockIdx.x & 7; }
    else            { widx = 3;               bn = blockIdx.x; }
    const int bm  = blockIdx.y;
    const int tid = threadIdx.x;
    const int wid = tid >> 5;
    const int l   = tid & 31;
    const int wm  = wid & 3;            // 4 x 32 rows
    const int wn  = wid >> 2;           // 2 x 64 cols
    const uint32_t sb = smem_u32(smem);

    float accf[2][8][4];
    #pragma unroll
    for (int i = 0; i < 2; i++)
        #pragma unroll
        for (int j = 0; j < 8; j++)
            #pragma unroll
            for (int c = 0; c < 4; c++) accf[i][j][c] = 0.f;

    load_stage<AMODE>(sb, 0, 0, bm, bn, widx, tid);
    asm volatile("cp.async.commit_group;");
    load_stage<AMODE>(sb, 1, 1, bm, bn, widx, tid);
    asm volatile("cp.async.commit_group;");

    for (int kt = 0; kt < KTILES; ++kt) {
        if (kt + 2 < KTILES) {
            asm volatile("cp.async.wait_group 1;");
            __syncthreads();
            load_stage<AMODE>(sb, (kt + 2) % 3, kt + 2, bm, bn, widx, tid);
            asm volatile("cp.async.commit_group;");
        } else {
            asm volatile("cp.async.wait_group 0;");
            __syncthreads();
        }

        const uint32_t st = sb + (kt % 3) * STG;
        uint32_t Ah[2][4], Al[2][4];
        #pragma unroll
        for (int i = 0; i < 2; i++) {
            ldsm4(Ah[i][0], Ah[i][1], Ah[i][2], Ah[i][3],
                  lda(st, wm * 32 + i * 16, 0, l));
            ldsm4(Al[i][0], Al[i][1], Al[i][2], Al[i][3],
                  lda(st, wm * 32 + i * 16, 4, l));
        }
        #pragma unroll
        for (int g = 0; g < 4; ++g) {
            uint32_t Bh[4], Bl[4];
            ldsm4(Bh[0], Bh[1], Bh[2], Bh[3], lda(st, wn * 64 + g * 16, 2, l));
            ldsm4(Bl[0], Bl[1], Bl[2], Bl[3], lda(st, wn * 64 + g * 16, 6, l));
            // pass-major issue: same-accumulator HMMAs are 4 apart.
            // pass hh
            mma16816(accf[0][2*g],   Ah[0][0], Ah[0][1], Ah[0][2], Ah[0][3], Bh[0], Bh[2]);
            mma16816(accf[1][2*g],   Ah[1][0], Ah[1][1], Ah[1][2], Ah[1][3], Bh[0], Bh[2]);
            mma16816(accf[0][2*g+1], Ah[0][0], Ah[0][1], Ah[0][2], Ah[0][3], Bh[1], Bh[3]);
            mma16816(accf[1][2*g+1], Ah[1][0], Ah[1][1], Ah[1][2], Ah[1][3], Bh[1], Bh[3]);
            // pass hl
            mma16816(accf[0][2*g],   Ah[0][0], Ah[0][1], Ah[0][2], Ah[0][3], Bl[0], Bl[2]);
            mma16816(accf[1][2*g],   Ah[1][0], Ah[1][1], Ah[1][2], Ah[1][3], Bl[0], Bl[2]);
            mma16816(accf[0][2*g+1], Ah[0][0], Ah[0][1], Ah[0][2], Ah[0][3], Bl[1], Bl[3]);
            mma16816(accf[1][2*g+1], Ah[1][0], Ah[1][1], Ah[1][2], Ah[1][3], Bl[1], Bl[3]);
            // pass lh
            mma16816(accf[0][2*g],   Al[0][0], Al[0][1], Al[0][2], Al[0][3], Bh[0], Bh[2]);
            mma16816(accf[1][2*g],   Al[1][0], Al[1][1], Al[1][2], Al[1][3], Bh[0], Bh[2]);
            mma16816(accf[0][2*g+1], Al[0][0], Al[0][1], Al[0][2], Al[0][3], Bh[1], Bh[3]);
            mma16816(accf[1][2*g+1], Al[1][0], Al[1][1], Al[1][2], Al[1][3], Bh[1], Bh[3]);
        }
        __syncthreads();
    }

    // epilogue: acc rows (l>>2, +8), cols (l&3)*2 — an even/odd RoPE pair.
    const int r0 = (l >> 2);
    const int cb = (l & 3) * 2;
    if (AMODE == 1) {
        #pragma unroll
        for (int i = 0; i < 2; i++)
            #pragma unroll
            for (int j = 0; j < 8; j++) {
                int gr0 = bm * 128 + wm * 32 + i * 16 + r0;
                int gc  = bn * 128 + wn * 64 + j * 8 + cb;
                *(float2*)(Cout + gr0 * DIM + gc) =
                    make_float2(accf[i][j][0], accf[i][j][1]);
                *(float2*)(Cout + (gr0 + 8) * DIM + gc) =
                    make_float2(accf[i][j][2], accf[i][j][3]);
            }
    } else {
        uint32_t* ph = (uint32_t*)((widx == 0) ? g_qh : (widx == 1) ? g_kh : g_vh);
        uint32_t* pl = (uint32_t*)((widx == 0) ? g_ql : (widx == 1) ? g_kl : g_vl);
        const bool rope = (widx < 2);
        #pragma unroll
        for (int i = 0; i < 2; i++)
            #pragma unroll
            for (int j = 0; j < 8; j++) {
                int gc   = bn * 128 + wn * 64 + j * 8 + cb;
                int head = gc >> 6, pi = (gc & 63) >> 1;
                #pragma unroll
                for (int half = 0; half < 2; ++half) {
                    int gr = bm * 128 + wm * 32 + i * 16 + r0 + half * 8;
                    float a0 = accf[i][j][half * 2];
                    float a1 = accf[i][j][half * 2 + 1];
                    int bq = gr >> 11, srow = gr & (SEQ - 1);
                    float oe = a0, oo = a1;
                    if (rope) {
                        float2 cs = g_cs[(srow << 5) + pi];
                        oe = cs.x * a0 - cs.y * a1;
                        oo = cs.y * a0 + cs.x * a1;
                    }
                    uint32_t h = bf2(oe, oo);
                    float fe = __uint_as_float(h << 16);
                    float fo = __uint_as_float(h & 0xffff0000u);
                    uint32_t lo = bf2(oe - fe, oo - fo);
                    int wi = ((((bq << 4) + head) * SEQ + srow) << 5) + pi;
                    ph[wi] = h;
                    pl[wi] = lo;
                }
            }
    }
}

// ---------------------------------------------------------------------------
// FA2 attention with raw mma.sync — pass-major HMMA order in QK and PV.
// ---------------------------------------------------------------------------
__global__ __launch_bounds__(128)
void attn_mma_kernel() {
    __shared__ __align__(16) uint4 sbuf4[2048];     // 32 KB
    char* sb = (char*)sbuf4;
    const uint32_t sbase = smem_u32(sb);
    const uint32_t bKh = 0, bKl = 8192, bVh = 16384, bVl = 24576;

    const int qt  = (int)(gridDim.x - 1 - blockIdx.x);
    const int bh  = blockIdx.y;
    const int tid = threadIdx.x;
    const int w   = tid >> 5;
    const int l   = tid & 31;

    const int qoff = (bh * SEQ + qt * 64) * DKH;

    {
        const uint4* qh = (const uint4*)(g_qh + qoff);
        const uint4* ql = (const uint4*)(g_ql + qoff);
        #pragma unroll
        for (int j = 0; j < 4; ++j) {
            int u = tid + j * 128;
            int row = u >> 3, c = u & 7;
            uint32_t so = ((row << 3) + (c ^ (row & 7))) << 4;
            *(uint4*)(sb + bKh + so) = qh[u];
            *(uint4*)(sb + bKl + so) = ql[u];
        }
    }
    __syncthreads();

    uint32_t Qh[4][4], Ql[4][4];
    #pragma unroll
    for (int kc = 0; kc < 4; ++kc) {
        ldsm4(Qh[kc][0], Qh[kc][1], Qh[kc][2], Qh[kc][3],
              lda(sbase + bKh, w * 16, kc * 2, l));
        ldsm4(Ql[kc][0], Ql[kc][1], Ql[kc][2], Ql[kc][3],
              lda(sbase + bKl, w * 16, kc * 2, l));
    }
    __syncthreads();

    float O[8][4];
    #pragma unroll
    for (int j = 0; j < 8; ++j)
        #pragma unroll
        for (int c = 0; c < 4; ++c) O[j][c] = 0.f;
    float M0 = -INFINITY, M1 = -INFINITY, L0 = 0.f, L1 = 0.f;

    const int rr0 = w * 16 + (l >> 2);
    const int rr1 = rr0 + 8;
    const int kb  = (l & 3) * 2;

    for (int kt = 0; kt <= qt; ++kt) {
        {
            const int koff = (bh * SEQ + kt * 64) * DKH;
            const uint4* s0 = (const uint4*)(g_kh + koff);
            const uint4* s1 = (const uint4*)(g_kl + koff);
            const uint4* s2 = (const uint4*)(g_vh + koff);
            const uint4* s3 = (const uint4*)(g_vl + koff);
            #pragma unroll
            for (int j = 0; j < 4; ++j) {
                int u = tid + j * 128;
                int row = u >> 3, c = u & 7;
                uint32_t so = ((row << 3) + (c ^ (row & 7))) << 4;
                *(uint4*)(sb + bKh + so) = s0[u];
                *(uint4*)(sb + bKl + so) = s1[u];
                *(uint4*)(sb + bVh + so) = s2[u];
                *(uint4*)(sb + bVl + so) = s3[u];
            }
        }
        __syncthreads();

        float S[8][4];
        #pragma unroll
        for (int t = 0; t < 8; ++t)
            #pragma unroll
            for (int c = 0; c < 4; ++c) S[t][c] = 0.f;

        #pragma unroll
        for (int kc = 0; kc < 4; ++kc) {
            #pragma unroll
            for (int kg = 0; kg < 4; ++kg) {
                uint32_t kh[4], klr[4];
                ldsm4(kh[0], kh[1], kh[2], kh[3],
                      lda(sbase + bKh, kg * 16, kc * 2, l));
                ldsm4(klr[0], klr[1], klr[2], klr[3],
                      lda(sbase + bKl, kg * 16, kc * 2, l));
                // pass-major: same-acc HMMAs 2 apart
                mma16816(S[2*kg],   Qh[kc][0], Qh[kc][1], Qh[kc][2], Qh[kc][3], kh[0],  kh[2]);
                mma16816(S[2*kg+1], Qh[kc][0], Qh[kc][1], Qh[kc][2], Qh[kc][3], kh[1],  kh[3]);
                mma16816(S[2*kg],   Qh[kc][0], Qh[kc][1], Qh[kc][2], Qh[kc][3], klr[0], klr[2]);
                mma16816(S[2*kg+1], Qh[kc][0], Qh[kc][1], Qh[kc][2], Qh[kc][3], klr[1], klr[3]);
                mma16816(S[2*kg],   Ql[kc][0], Ql[kc][1], Ql[kc][2], Ql[kc][3], kh[0],  kh[2]);
                mma16816(S[2*kg+1], Ql[kc][0], Ql[kc][1], Ql[kc][2], Ql[kc][3], kh[1],  kh[3]);
            }
        }

        const bool diag = (kt == qt);
        #pragma unroll
        for (int t = 0; t < 8; ++t) {
            #pragma unroll
            for (int c = 0; c < 4; ++c) {
                float s = S[t][c] * 0.125f;
                if (diag) {
                    int key = t * 8 + kb + (c & 1);
                    int row = (c < 2) ? rr0 : rr1;
                    if (key > row) s = -INFINITY;
                }
                S[t][c] = s;
            }
        }

        float m0 = -INFINITY, m1 = -INFINITY;
        #pragma unroll
        for (int t = 0; t < 8; ++t) {
            m0 = fmaxf(m0, fmaxf(S[t][0], S[t][1]));
            m1 = fmaxf(m1, fmaxf(S[t][2], S[t][3]));
        }
        m0 = fmaxf(m0, __shfl_xor_sync(0xffffffffu, m0, 1));
        m0 = fmaxf(m0, __shfl_xor_sync(0xffffffffu, m0, 2));
        m1 = fmaxf(m1, __shfl_xor_sync(0xffffffffu, m1, 1));
        m1 = fmaxf(m1, __shfl_xor_sync(0xffffffffu, m1, 2));
        float Mn0 = fmaxf(M0, m0), Mn1 = fmaxf(M1, m1);
        float al0 = __expf(M0 - Mn0), al1 = __expf(M1 - Mn1);
        M0 = Mn0; M1 = Mn1;
        float rs0 = 0.f, rs1 = 0.f;
        #pragma unroll
        for (int t = 0; t < 8; ++t) {
            S[t][0] = __expf(S[t][0] - Mn0);
            S[t][1] = __expf(S[t][1] - Mn0);
            S[t][2] = __expf(S[t][2] - Mn1);
            S[t][3] = __expf(S[t][3] - Mn1);
            rs0 += S[t][0] + S[t][1];
            rs1 += S[t][2] + S[t][3];
        }
        rs0 += __shfl_xor_sync(0xffffffffu, rs0, 1);
        rs0 += __shfl_xor_sync(0xffffffffu, rs0, 2);
        rs1 += __shfl_xor_sync(0xffffffffu, rs1, 1);
        rs1 += __shfl_xor_sync(0xffffffffu, rs1, 2);
        L0 = L0 * al0 + rs0;
        L1 = L1 * al1 + rs1;
        #pragma unroll
        for (int j = 0; j < 8; ++j) {
            O[j][0] *= al0; O[j][1] *= al0;
            O[j][2] *= al1; O[j][3] *= al1;
        }

        #pragma unroll
        for (int kc = 0; kc < 4; ++kc) {
            uint32_t pa0 = bf2(S[2*kc][0],   S[2*kc][1]);
            uint32_t pa1 = bf2(S[2*kc][2],   S[2*kc][3]);
            uint32_t pa2 = bf2(S[2*kc+1][0], S[2*kc+1][1]);
            uint32_t pa3 = bf2(S[2*kc+1][2], S[2*kc+1][3]);
            float f, fg;
            uint32_t pl0, pl1, pl2, pl3;
            f = __uint_as_float(pa0 << 16);
            fg = __uint_as_float(pa0 & 0xffff0000u);
            pl0 = bf2(S[2*kc][0] - f, S[2*kc][1] - fg);
            f = __uint_as_float(pa1 << 16);
            fg = __uint_as_float(pa1 & 0xffff0000u);
            pl1 = bf2(S[2*kc][2] - f, S[2*kc][3] - fg);
            f = __uint_as_float(pa2 << 16);
            fg = __uint_as_float(pa2 & 0xffff0000u);
            pl2 = bf2(S[2*kc+1][0] - f, S[2*kc+1][1] - fg);
            f = __uint_as_float(pa3 << 16);
            fg = __uint_as_float(pa3 & 0xffff0000u);
            pl3 = bf2(S[2*kc+1][2] - f, S[2*kc+1][3] - fg);

            #pragma unroll
            for (int j2 = 0; j2 < 4; ++j2) {
                uint32_t vh[4], vl[4];
                ldsm4t(vh[0], vh[1], vh[2], vh[3],
                       lda(sbase + bVh, kc * 16, j2 * 2, l));
                ldsm4t(vl[0], vl[1], vl[2], vl[3],
                       lda(sbase + bVl, kc * 16, j2 * 2, l));
                // pass-major: same-acc HMMAs 2 apart
                mma16816(O[2*j2],   pa0, pa1, pa2, pa3, vh[0], vh[1]);
                mma16816(O[2*j2+1], pa0, pa1, pa2, pa3, vh[2], vh[3]);
                mma16816(O[2*j2],   pa0, pa1, pa2, pa3, vl[0], vl[1]);
                mma16816(O[2*j2+1], pa0, pa1, pa2, pa3, vl[2], vl[3]);
                mma16816(O[2*j2],   pl0, pl1, pl2, pl3, vh[0], vh[1]);
                mma16816(O[2*j2+1], pl0, pl1, pl2, pl3, vh[2], vh[3]);
            }
        }
        __syncthreads();
    }

    float inv0 = 1.f / L0, inv1 = 1.f / L1;
    uint32_t* oh = (uint32_t*)g_ath;
    uint32_t* ol = (uint32_t*)g_atl;
    #pragma unroll
    for (int j = 0; j < 8; ++j) {
        int col = j * 8 + kb;
        float a0 = O[j][0] * inv0, a1 = O[j][1] * inv0;
        uint32_t h0 = bf2(a0, a1);
        float fe = __uint_as_float(h0 << 16);
        float fo = __uint_as_float(h0 & 0xffff0000u);
        uint32_t l0w = bf2(a0 - fe, a1 - fo);
        int wi0 = (qoff + rr0 * DKH + col) >> 1;
        oh[wi0] = h0; ol[wi0] = l0w;

        float b0 = O[j][2] * inv1, b1 = O[j][3] * inv1;
        uint32_t h1 = bf2(b0, b1);
        fe = __uint_as_float(h1 << 16);
        fo = __uint_as_float(h1 & 0xffff0000u);
        uint32_t l1w = bf2(b0 - fe, b1 - fo);
        int wi1 = (qoff + rr1 * DKH + col) >> 1;
        oh[wi1] = h1; ol[wi1] = l1w;
    }
}

// ---------------------------------------------------------------------------
extern "C" void kernel_launch(void* const* d_in, const int* in_sizes, int n_in,
                              void* d_out, int out_size) {
    (void)in_sizes; (void)n_in; (void)out_size;
    const float* x   = (const float*)d_in[0];
    const float* Wq  = (const float*)d_in[1];
    const float* Wk  = (const float*)d_in[2];
    const float* Wv  = (const float*)d_in[3];
    const float* Wo  = (const float*)d_in[4];
    const int*   pos = (const int*)d_in[5];
    float* out = (float*)d_out;

    rope_table_kernel<<<(SEQ * 32 + 255) / 256, 256>>>(pos);
    split_x_kernel<<<(MTOT * DIM / 2) / 256, 256>>>(x);
    split_w_kernel<<<(4 * DIM * DIM / 2) / 256, 256>>>(Wq, Wk, Wv, Wo);

    // merged QKV with fused RoPE+split epilogue
    gemm_pipe_kernel<0><<<dim3(24, MTOT / 128), 256>>>(nullptr);

    attn_mma_kernel<<<dim3(SEQ / 64, NB * NH), 128>>>();

    gemm_pipe_kernel<1><<<dim3(8, MTOT / 128), 256>>>(out);
}

// round 17
// speedup vs baseline: 1.5464x; 1.5464x over previous
#include <cuda_runtime.h>
#include <cuda_bf16.h>
#include <math.h>
#include <stdint.h>

#define NB   4
#define SEQ  2048
#define DIM  1024
#define NH   16
#define DKH  64
#define MTOT (NB*SEQ)        // 8192
#define KTILES (DIM/16)      // 64

// Scratch (device globals: no allocations allowed)
__device__ float2 g_cs[SEQ*(DKH/2)];                           // (cos,sin)
__device__ __nv_bfloat16 g_xh[MTOT*DIM],  g_xl[MTOT*DIM];      // input x split
__device__ __nv_bfloat16 g_wh[4*DIM*DIM], g_wl[4*DIM*DIM];     // Wq,Wk,Wv,Wo split
__device__ __nv_bfloat16 g_qh[NB*NH*SEQ*DKH], g_ql[NB*NH*SEQ*DKH];
__device__ __nv_bfloat16 g_kh[NB*NH*SEQ*DKH], g_kl[NB*NH*SEQ*DKH];
__device__ __nv_bfloat16 g_vh[NB*NH*SEQ*DKH], g_vl[NB*NH*SEQ*DKH];
__device__ __nv_bfloat16 g_ath[NB*NH*SEQ*DKH], g_atl[NB*NH*SEQ*DKH];  // attn out

// ---------------------------------------------------------------------------
// Helpers
// ---------------------------------------------------------------------------
__device__ __forceinline__ uint32_t bf2(float lo, float hi) {
    uint32_t r;
    asm("cvt.rn.bf16x2.f32 %0, %1, %2;" : "=r"(r) : "f"(hi), "f"(lo));
    return r;
}

__device__ __forceinline__ uint32_t smem_u32(const void* p) {
    uint32_t a;
    asm("{ .reg .u64 t; cvta.to.shared.u64 t, %1; cvt.u32.u64 %0, t; }"
        : "=r"(a) : "l"(p));
    return a;
}

__device__ __forceinline__ void cpasync16(uint32_t dst, const void* src) {
    asm volatile("cp.async.cg.shared.global [%0], [%1], 16;"
                 :: "r"(dst), "l"(src));
}

__device__ __forceinline__ void ldsm4(uint32_t& r0, uint32_t& r1,
                                      uint32_t& r2, uint32_t& r3, uint32_t a) {
    asm volatile("ldmatrix.sync.aligned.m8n8.x4.shared.b16 {%0,%1,%2,%3}, [%4];"
                 : "=r"(r0), "=r"(r1), "=r"(r2), "=r"(r3) : "r"(a));
}
__device__ __forceinline__ void ldsm4t(uint32_t& r0, uint32_t& r1,
                                       uint32_t& r2, uint32_t& r3, uint32_t a) {
    asm volatile("ldmatrix.sync.aligned.m8n8.x4.trans.shared.b16 {%0,%1,%2,%3}, [%4];"
                 : "=r"(r0), "=r"(r1), "=r"(r2), "=r"(r3) : "r"(a));
}

// volatile is load-bearing: R15 showed non-volatile mma lets nvcc reschedule
// into register-spilling live ranges (497us -> 770us). Order via statement order.
__device__ __forceinline__ void mma16816(float d[4],
                                         uint32_t a0, uint32_t a1, uint32_t a2, uint32_t a3,
                                         uint32_t b0, uint32_t b1) {
    asm volatile(
        "mma.sync.aligned.m16n8k16.row.col.f32.bf16.bf16.f32 "
        "{%0,%1,%2,%3}, {%4,%5,%6,%7}, {%8,%9}, {%0,%1,%2,%3};"
        : "+f"(d[0]), "+f"(d[1]), "+f"(d[2]), "+f"(d[3])
        : "r"(a0), "r"(a1), "r"(a2), "r"(a3), "r"(b0), "r"(b1));
}

// swizzled address of a 16B unit in a [rows][8 units(128B)] region,
// laid out for ldmatrix x4 of a 16-row x 2-unit tile at (row0, cbase).
__device__ __forceinline__ uint32_t lda(uint32_t base, int row0, int cbase, int lane) {
    int g = lane >> 3, r = lane & 7;
    int row = row0 + ((g & 1) << 3) + r;
    int c = cbase + (g >> 1);
    return base + (((row << 3) + (c ^ (row & 7))) << 4);
}

// ---------------------------------------------------------------------------
// RoPE table (packed cos/sin)
// ---------------------------------------------------------------------------
__global__ void rope_table_kernel(const int* __restrict__ pos) {
    int idx = blockIdx.x * blockDim.x + threadIdx.x;
    if (idx >= SEQ * (DKH/2)) return;
    int srow = idx >> 5;
    int i    = idx & 31;
    double freq = exp(-((double)(2*i) / (double)DKH) * log(10000.0));
    double ang  = (double)pos[srow] * freq;
    g_cs[idx] = make_float2((float)cos(ang), (float)sin(ang));
}

// ---------------------------------------------------------------------------
// Pre-split kernels: fp32 -> bf16 hi/lo planes
// ---------------------------------------------------------------------------
__global__ void split_x_kernel(const float* __restrict__ x) {
    int idx = blockIdx.x * blockDim.x + threadIdx.x;   // < MTOT*DIM/2
    float2 v = *(const float2*)(x + idx * 2);
    uint32_t h = bf2(v.x, v.y);
    float fe = __uint_as_float(h << 16);
    float fo = __uint_as_float(h & 0xffff0000u);
    ((uint32_t*)g_xh)[idx] = h;
    ((uint32_t*)g_xl)[idx] = bf2(v.x - fe, v.y - fo);
}

__global__ void split_w_kernel(const float* __restrict__ Wq,
                               const float* __restrict__ Wk,
                               const float* __restrict__ Wv,
                               const float* __restrict__ Wo) {
    int idx = blockIdx.x * blockDim.x + threadIdx.x;   // < 4*DIM*DIM/2
    int t = idx >> 19;
    int r = idx & ((1 << 19) - 1);
    const float* W = (t == 0) ? Wq : (t == 1) ? Wk : (t == 2) ? Wv : Wo;
    float2 v = *(const float2*)(W + r * 2);
    uint32_t h = bf2(v.x, v.y);
    float fe = __uint_as_float(h << 16);
    float fo = __uint_as_float(h & 0xffff0000u);
    ((uint32_t*)g_wh)[idx] = h;
    ((uint32_t*)g_wl)[idx] = bf2(v.x - fe, v.y - fo);
}

// ---------------------------------------------------------------------------
// cp.async 3-stage pipelined raw-mma NT GEMM on pre-split planes, 3-pass,
// single sync per iteration, pass-major HMMA statement order (volatile).
// Block 128x128, BK=16, 8 warps (warp tile 32x64). 48KB static smem.
// Stage row r (128B): units [0-1]=Ah, [2-3]=Bh, [4-5]=Al, [6-7]=Bl (swizzled).
// AMODE 0 (QKV): A = g_xh/g_xl; epilogue applies RoPE (widx<2) and writes
//                split bf16 planes g_{q,k,v}{h,l} in bhsd layout.
// AMODE 1 (Wo):  A = g_ath/g_atl bhsd gather; epilogue writes fp32 out.
// ---------------------------------------------------------------------------
#define STG 16384

template<int AMODE>
__device__ __forceinline__ void load_stage(uint32_t sb, int stage, int kt,
                                           int bm, int bn, int widx, int tid) {
    uint32_t st = sb + stage * STG;
    #pragma unroll
    for (int j = 0; j < 4; ++j) {
        int c   = tid + j * 256;           // 0..1023
        int row = c >> 3;
        int u   = c & 7;
        int k   = kt * 16 + (u & 1) * 8;
        const __nv_bfloat16* src;
        if ((u & 6) == 2) {
            src = g_wh + widx * (DIM * DIM) + (bn * 128 + row) * DIM + k;
        } else if ((u & 6) == 6) {
            src = g_wl + widx * (DIM * DIM) + (bn * 128 + row) * DIM + k;
        } else {
            const __nv_bfloat16* base;
            if (AMODE == 0) base = (u & 4) ? g_xl : g_xh;
            else            base = (u & 4) ? g_atl : g_ath;
            int aRow = bm * 128 + row;
            if (AMODE == 0) {
                src = base + aRow * DIM + k;
            } else {
                int head = k >> 6, koff = k & 63;
                int bq = aRow >> 11, srow = aRow & (SEQ - 1);
                src = base + (((bq << 4) + head) * SEQ + srow) * DKH + koff;
            }
        }
        uint32_t dst = st + (((row << 3) + (u ^ (row & 7))) << 4);
        cpasync16(dst, src);
    }
}

template<int AMODE>
__global__ __launch_bounds__(256, 2)
void gemm_pipe_kernel(float* __restrict__ Cout) {
    __shared__ __align__(16) char smem[3 * STG];   // 48KB

    int widx, bn;
    if (AMODE == 0) { widx = blockIdx.x >> 3; bn = blockIdx.x & 7; }
    else            { widx = 3;               bn = blockIdx.x; }
    const int bm  = blockIdx.y;
    const int tid = threadIdx.x;
    const int wid = tid >> 5;
    const int l   = tid & 31;
    const int wm  = wid & 3;            // 4 x 32 rows
    const int wn  = wid >> 2;           // 2 x 64 cols
    const uint32_t sb = smem_u32(smem);

    float accf[2][8][4];
    #pragma unroll
    for (int i = 0; i < 2; i++)
        #pragma unroll
        for (int j = 0; j < 8; j++)
            #pragma unroll
            for (int c = 0; c < 4; c++) accf[i][j][c] = 0.f;

    load_stage<AMODE>(sb, 0, 0, bm, bn, widx, tid);
    asm volatile("cp.async.commit_group;");
    load_stage<AMODE>(sb, 1, 1, bm, bn, widx, tid);
    asm volatile("cp.async.commit_group;");

    for (int kt = 0; kt < KTILES; ++kt) {
        if (kt + 2 < KTILES) {
            asm volatile("cp.async.wait_group 1;");
            __syncthreads();
            load_stage<AMODE>(sb, (kt + 2) % 3, kt + 2, bm, bn, widx, tid);
            asm volatile("cp.async.commit_group;");
        } else {
            asm volatile("cp.async.wait_group 0;");
            __syncthreads();
        }

        const uint32_t st = sb + (kt % 3) * STG;
        uint32_t Ah[2][4], Al[2][4];
        #pragma unroll
        for (int i = 0; i < 2; i++) {
            ldsm4(Ah[i][0], Ah[i][1], Ah[i][2], Ah[i][3],
                  lda(st, wm * 32 + i * 16, 0, l));
            ldsm4(Al[i][0], Al[i][1], Al[i][2], Al[i][3],
                  lda(st, wm * 32 + i * 16, 4, l));
        }
        #pragma unroll
        for (int g = 0; g < 4; ++g) {
            uint32_t Bh[4], Bl[4];
            ldsm4(Bh[0], Bh[1], Bh[2], Bh[3], lda(st, wn * 64 + g * 16, 2, l));
            ldsm4(Bl[0], Bl[1], Bl[2], Bl[3], lda(st, wn * 64 + g * 16, 6, l));
            // pass-major statement order: same-accumulator HMMAs 4 apart.
            // pass hh
            mma16816(accf[0][2*g],   Ah[0][0], Ah[0][1], Ah[0][2], Ah[0][3], Bh[0], Bh[2]);
            mma16816(accf[1][2*g],   Ah[1][0], Ah[1][1], Ah[1][2], Ah[1][3], Bh[0], Bh[2]);
            mma16816(accf[0][2*g+1], Ah[0][0], Ah[0][1], Ah[0][2], Ah[0][3], Bh[1], Bh[3]);
            mma16816(accf[1][2*g+1], Ah[1][0], Ah[1][1], Ah[1][2], Ah[1][3], Bh[1], Bh[3]);
            // pass hl
            mma16816(accf[0][2*g],   Ah[0][0], Ah[0][1], Ah[0][2], Ah[0][3], Bl[0], Bl[2]);
            mma16816(accf[1][2*g],   Ah[1][0], Ah[1][1], Ah[1][2], Ah[1][3], Bl[0], Bl[2]);
            mma16816(accf[0][2*g+1], Ah[0][0], Ah[0][1], Ah[0][2], Ah[0][3], Bl[1], Bl[3]);
            mma16816(accf[1][2*g+1], Ah[1][0], Ah[1][1], Ah[1][2], Ah[1][3], Bl[1], Bl[3]);
            // pass lh
            mma16816(accf[0][2*g],   Al[0][0], Al[0][1], Al[0][2], Al[0][3], Bh[0], Bh[2]);
            mma16816(accf[1][2*g],   Al[1][0], Al[1][1], Al[1][2], Al[1][3], Bh[0], Bh[2]);
            mma16816(accf[0][2*g+1], Al[0][0], Al[0][1], Al[0][2], Al[0][3], Bh[1], Bh[3]);
            mma16816(accf[1][2*g+1], Al[1][0], Al[1][1], Al[1][2], Al[1][3], Bh[1], Bh[3]);
        }
        __syncthreads();
    }

    // epilogue: acc rows (l>>2, +8), cols (l&3)*2 — an even/odd RoPE pair.
    const int r0 = (l >> 2);
    const int cb = (l & 3) * 2;
    if (AMODE == 1) {
        #pragma unroll
        for (int i = 0; i < 2; i++)
            #pragma unroll
            for (int j = 0; j < 8; j++) {
                int gr0 = bm * 128 + wm * 32 + i * 16 + r0;
                int gc  = bn * 128 + wn * 64 + j * 8 + cb;
                *(float2*)(Cout + gr0 * DIM + gc) =
                    make_float2(accf[i][j][0], accf[i][j][1]);
                *(float2*)(Cout + (gr0 + 8) * DIM + gc) =
                    make_float2(accf[i][j][2], accf[i][j][3]);
            }
    } else {
        uint32_t* ph = (uint32_t*)((widx == 0) ? g_qh : (widx == 1) ? g_kh : g_vh);
        uint32_t* pl = (uint32_t*)((widx == 0) ? g_ql : (widx == 1) ? g_kl : g_vl);
        const bool rope = (widx < 2);
        #pragma unroll
        for (int i = 0; i < 2; i++)
            #pragma unroll
            for (int j = 0; j < 8; j++) {
                int gc   = bn * 128 + wn * 64 + j * 8 + cb;
                int head = gc >> 6, pi = (gc & 63) >> 1;
                #pragma unroll
                for (int half = 0; half < 2; ++half) {
                    int gr = bm * 128 + wm * 32 + i * 16 + r0 + half * 8;
                    float a0 = accf[i][j][half * 2];
                    float a1 = accf[i][j][half * 2 + 1];
                    int bq = gr >> 11, srow = gr & (SEQ - 1);
                    float oe = a0, oo = a1;
                    if (rope) {
                        float2 cs = g_cs[(srow << 5) + pi];
                        oe = cs.x * a0 - cs.y * a1;
                        oo = cs.y * a0 + cs.x * a1;
                    }
                    uint32_t h = bf2(oe, oo);
                    float fe = __uint_as_float(h << 16);
                    float fo = __uint_as_float(h & 0xffff0000u);
                    uint32_t lo = bf2(oe - fe, oo - fo);
                    int wi = ((((bq << 4) + head) * SEQ + srow) << 5) + pi;
                    ph[wi] = h;
                    pl[wi] = lo;
                }
            }
    }
}

// ---------------------------------------------------------------------------
// FA2 attention with raw mma.sync — pass-major statement order (volatile).
// ---------------------------------------------------------------------------
__global__ __launch_bounds__(128)
void attn_mma_kernel() {
    __shared__ __align__(16) uint4 sbuf4[2048];     // 32 KB
    char* sb = (char*)sbuf4;
    const uint32_t sbase = smem_u32(sb);
    const uint32_t bKh = 0, bKl = 8192, bVh = 16384, bVl = 24576;

    const int qt  = (int)(gridDim.x - 1 - blockIdx.x);
    const int bh  = blockIdx.y;
    const int tid = threadIdx.x;
    const int w   = tid >> 5;
    const int l   = tid & 31;

    const int qoff = (bh * SEQ + qt * 64) * DKH;

    {
        const uint4* qh = (const uint4*)(g_qh + qoff);
        const uint4* ql = (const uint4*)(g_ql + qoff);
        #pragma unroll
        for (int j = 0; j < 4; ++j) {
            int u = tid + j * 128;
            int row = u >> 3, c = u & 7;
            uint32_t so = ((row << 3) + (c ^ (row & 7))) << 4;
            *(uint4*)(sb + bKh + so) = qh[u];
            *(uint4*)(sb + bKl + so) = ql[u];
        }
    }
    __syncthreads();

    uint32_t Qh[4][4], Ql[4][4];
    #pragma unroll
    for (int kc = 0; kc < 4; ++kc) {
        ldsm4(Qh[kc][0], Qh[kc][1], Qh[kc][2], Qh[kc][3],
              lda(sbase + bKh, w * 16, kc * 2, l));
        ldsm4(Ql[kc][0], Ql[kc][1], Ql[kc][2], Ql[kc][3],
              lda(sbase + bKl, w * 16, kc * 2, l));
    }
    __syncthreads();

    float O[8][4];
    #pragma unroll
    for (int j = 0; j < 8; ++j)
        #pragma unroll
        for (int c = 0; c < 4; ++c) O[j][c] = 0.f;
    float M0 = -INFINITY, M1 = -INFINITY, L0 = 0.f, L1 = 0.f;

    const int rr0 = w * 16 + (l >> 2);
    const int rr1 = rr0 + 8;
    const int kb  = (l & 3) * 2;

    for (int kt = 0; kt <= qt; ++kt) {
        {
            const int koff = (bh * SEQ + kt * 64) * DKH;
            const uint4* s0 = (const uint4*)(g_kh + koff);
            const uint4* s1 = (const uint4*)(g_kl + koff);
            const uint4* s2 = (const uint4*)(g_vh + koff);
            const uint4* s3 = (const uint4*)(g_vl + koff);
            #pragma unroll
            for (int j = 0; j < 4; ++j) {
                int u = tid + j * 128;
                int row = u >> 3, c = u & 7;
                uint32_t so = ((row << 3) + (c ^ (row & 7))) << 4;
                *(uint4*)(sb + bKh + so) = s0[u];
                *(uint4*)(sb + bKl + so) = s1[u];
                *(uint4*)(sb + bVh + so) = s2[u];
                *(uint4*)(sb + bVl + so) = s3[u];
            }
        }
        __syncthreads();

        float S[8][4];
        #pragma unroll
        for (int t = 0; t < 8; ++t)
            #pragma unroll
            for (int c = 0; c < 4; ++c) S[t][c] = 0.f;

        #pragma unroll
        for (int kc = 0; kc < 4; ++kc) {
            #pragma unroll
            for (int kg = 0; kg < 4; ++kg) {
                uint32_t kh[4], klr[4];
                ldsm4(kh[0], kh[1], kh[2], kh[3],
                      lda(sbase + bKh, kg * 16, kc * 2, l));
                ldsm4(klr[0], klr[1], klr[2], klr[3],
                      lda(sbase + bKl, kg * 16, kc * 2, l));
                // pass-major: same-acc HMMAs 2 apart
                mma16816(S[2*kg],   Qh[kc][0], Qh[kc][1], Qh[kc][2], Qh[kc][3], kh[0],  kh[2]);
                mma16816(S[2*kg+1], Qh[kc][0], Qh[kc][1], Qh[kc][2], Qh[kc][3], kh[1],  kh[3]);
                mma16816(S[2*kg],   Qh[kc][0], Qh[kc][1], Qh[kc][2], Qh[kc][3], klr[0], klr[2]);
                mma16816(S[2*kg+1], Qh[kc][0], Qh[kc][1], Qh[kc][2], Qh[kc][3], klr[1], klr[3]);
                mma16816(S[2*kg],   Ql[kc][0], Ql[kc][1], Ql[kc][2], Ql[kc][3], kh[0],  kh[2]);
                mma16816(S[2*kg+1], Ql[kc][0], Ql[kc][1], Ql[kc][2], Ql[kc][3], kh[1],  kh[3]);
            }
        }

        const bool diag = (kt == qt);
        #pragma unroll
        for (int t = 0; t < 8; ++t) {
            #pragma unroll
            for (int c = 0; c < 4; ++c) {
                float s = S[t][c] * 0.125f;
                if (diag) {
                    int key = t * 8 + kb + (c & 1);
                    int row = (c < 2) ? rr0 : rr1;
                    if (key > row) s = -INFINITY;
                }
                S[t][c] = s;
            }
        }

        float m0 = -INFINITY, m1 = -INFINITY;
        #pragma unroll
        for (int t = 0; t < 8; ++t) {
            m0 = fmaxf(m0, fmaxf(S[t][0], S[t][1]));
            m1 = fmaxf(m1, fmaxf(S[t][2], S[t][3]));
        }
        m0 = fmaxf(m0, __shfl_xor_sync(0xffffffffu, m0, 1));
        m0 = fmaxf(m0, __shfl_xor_sync(0xffffffffu, m0, 2));
        m1 = fmaxf(m1, __shfl_xor_sync(0xffffffffu, m1, 1));
        m1 = fmaxf(m1, __shfl_xor_sync(0xffffffffu, m1, 2));
        float Mn0 = fmaxf(M0, m0), Mn1 = fmaxf(M1, m1);
        float al0 = __expf(M0 - Mn0), al1 = __expf(M1 - Mn1);
        M0 = Mn0; M1 = Mn1;
        float rs0 = 0.f, rs1 = 0.f;
        #pragma unroll
        for (int t = 0; t < 8; ++t) {
            S[t][0] = __expf(S[t][0] - Mn0);
            S[t][1] = __expf(S[t][1] - Mn0);
            S[t][2] = __expf(S[t][2] - Mn1);
            S[t][3] = __expf(S[t][3] - Mn1);
            rs0 += S[t][0] + S[t][1];
            rs1 += S[t][2] + S[t][3];
        }
        rs0 += __shfl_xor_sync(0xffffffffu, rs0, 1);
        rs0 += __shfl_xor_sync(0xffffffffu, rs0, 2);
        rs1 += __shfl_xor_sync(0xffffffffu, rs1, 1);
        rs1 += __shfl_xor_sync(0xffffffffu, rs1, 2);
        L0 = L0 * al0 + rs0;
        L1 = L1 * al1 + rs1;
        #pragma unroll
        for (int j = 0; j < 8; ++j) {
            O[j][0] *= al0; O[j][1] *= al0;
            O[j][2] *= al1; O[j][3] *= al1;
        }

        #pragma unroll
        for (int kc = 0; kc < 4; ++kc) {
            uint32_t pa0 = bf2(S[2*kc][0],   S[2*kc][1]);
            uint32_t pa1 = bf2(S[2*kc][2],   S[2*kc][3]);
            uint32_t pa2 = bf2(S[2*kc+1][0], S[2*kc+1][1]);
            uint32_t pa3 = bf2(S[2*kc+1][2], S[2*kc+1][3]);
            float f, fg;
            uint32_t pl0, pl1, pl2, pl3;
            f = __uint_as_float(pa0 << 16);
            fg = __uint_as_float(pa0 & 0xffff0000u);
            pl0 = bf2(S[2*kc][0] - f, S[2*kc][1] - fg);
            f = __uint_as_float(pa1 << 16);
            fg = __uint_as_float(pa1 & 0xffff0000u);
            pl1 = bf2(S[2*kc][2] - f, S[2*kc][3] - fg);
            f = __uint_as_float(pa2 << 16);
            fg = __uint_as_float(pa2 & 0xffff0000u);
            pl2 = bf2(S[2*kc+1][0] - f, S[2*kc+1][1] - fg);
            f = __uint_as_float(pa3 << 16);
            fg = __uint_as_float(pa3 & 0xffff0000u);
            pl3 = bf2(S[2*kc+1][2] - f, S[2*kc+1][3] - fg);

            #pragma unroll
            for (int j2 = 0; j2 < 4; ++j2) {
                uint32_t vh[4], vl[4];
                ldsm4t(vh[0], vh[1], vh[2], vh[3],
                       lda(sbase + bVh, kc * 16, j2 * 2, l));
                ldsm4t(vl[0], vl[1], vl[2], vl[3],
                       lda(sbase + bVl, kc * 16, j2 * 2, l));
                // pass-major: same-acc HMMAs 2 apart
                mma16816(O[2*j2],   pa0, pa1, pa2, pa3, vh[0], vh[1]);
                mma16816(O[2*j2+1], pa0, pa1, pa2, pa3, vh[2], vh[3]);
                mma16816(O[2*j2],   pa0, pa1, pa2, pa3, vl[0], vl[1]);
                mma16816(O[2*j2+1], pa0, pa1, pa2, pa3, vl[2], vl[3]);
                mma16816(O[2*j2],   pl0, pl1, pl2, pl3, vh[0], vh[1]);
                mma16816(O[2*j2+1], pl0, pl1, pl2, pl3, vh[2], vh[3]);
            }
        }
        __syncthreads();
    }

    float inv0 = 1.f / L0, inv1 = 1.f / L1;
    uint32_t* oh = (uint32_t*)g_ath;
    uint32_t* ol = (uint32_t*)g_atl;
    #pragma unroll
    for (int j = 0; j < 8; ++j) {
        int col = j * 8 + kb;
        float a0 = O[j][0] * inv0, a1 = O[j][1] * inv0;
        uint32_t h0 = bf2(a0, a1);
        float fe = __uint_as_float(h0 << 16);
        float fo = __uint_as_float(h0 & 0xffff0000u);
        uint32_t l0w = bf2(a0 - fe, a1 - fo);
        int wi0 = (qoff + rr0 * DKH + col) >> 1;
        oh[wi0] = h0; ol[wi0] = l0w;

        float b0 = O[j][2] * inv1, b1 = O[j][3] * inv1;
        uint32_t h1 = bf2(b0, b1);
        fe = __uint_as_float(h1 << 16);
        fo = __uint_as_float(h1 & 0xffff0000u);
        uint32_t l1w = bf2(b0 - fe, b1 - fo);
        int wi1 = (qoff + rr1 * DKH + col) >> 1;
        oh[wi1] = h1; ol[wi1] = l1w;
    }
}

// ---------------------------------------------------------------------------
extern "C" void kernel_launch(void* const* d_in, const int* in_sizes, int n_in,
                              void* d_out, int out_size) {
    (void)in_sizes; (void)n_in; (void)out_size;
    const float* x   = (const float*)d_in[0];
    const float* Wq  = (const float*)d_in[1];
    const float* Wk  = (const float*)d_in[2];
    const float* Wv  = (const float*)d_in[3];
    const float* Wo  = (const float*)d_in[4];
    const int*   pos = (const int*)d_in[5];
    float* out = (float*)d_out;

    rope_table_kernel<<<(SEQ * 32 + 255) / 256, 256>>>(pos);
    split_x_kernel<<<(MTOT * DIM / 2) / 256, 256>>>(x);
    split_w_kernel<<<(4 * DIM * DIM / 2) / 256, 256>>>(Wq, Wk, Wv, Wo);

    // merged QKV with fused RoPE+split epilogue
    gemm_pipe_kernel<0><<<dim3(24, MTOT / 128), 256>>>(nullptr);

    attn_mma_kernel<<<dim3(SEQ / 64, NB * NH), 128>>>();

    gemm_pipe_kernel<1><<<dim3(8, MTOT / 128), 256>>>(out);
}